// round 8
// baseline (speedup 1.0000x reference)
#include <cuda_runtime.h>
#include <cuda_bf16.h>
#include <cstdint>

#define NNODES 20000
#define NEDGES 640000
#define IND    256
#define HID    128
#define NG     64

#define KBLK   139          // CTAs in split-K
#define KPADB  140          // padded partial count (index 139 zeroed)
#define NB     144          // nodes per CTA
#define NST    9            // stages of 16 nodes
#define RGRP   5            // reduce1 groups
#define RSPAN  28           // partials per reduce1 group (5*28 = 140)

// ---------------- device scratch ----------------
__device__ __align__(16) unsigned g_Cp[NNODES * 16];       // packed u8 counts [node][g], 1.25 MB
__device__ __align__(16) int      g_outdeg[NNODES];
__device__ __align__(16) int      g_cnt[NG];
__device__ __align__(16) float    g_part[KPADB][128][IND]; // split-K partials (18.3 MB)
__device__ __align__(16) float    g_r1[RGRP][128][IND];    // reduce1 partials
__device__ __align__(16) float    g_P[2][128][HID];        // layer activations

// ---------------- helpers ----------------
__device__ __forceinline__ uint32_t smem_u32(const void* p) {
    uint32_t a;
    asm("{ .reg .u64 t; cvta.to.shared.u64 t, %1; cvt.u32.u64 %0, t; }" : "=r"(a) : "l"(p));
    return a;
}
__device__ __forceinline__ void mma16816(float* d, uint32_t a0, uint32_t a1, uint32_t a2,
                                         uint32_t a3, uint32_t b0, uint32_t b1) {
    asm volatile(
        "mma.sync.aligned.m16n8k16.row.col.f32.bf16.bf16.f32 "
        "{%0,%1,%2,%3},{%4,%5,%6,%7},{%8,%9},{%0,%1,%2,%3};"
        : "+f"(d[0]), "+f"(d[1]), "+f"(d[2]), "+f"(d[3])
        : "r"(a0), "r"(a1), "r"(a2), "r"(a3), "r"(b0), "r"(b1));
}
__device__ __forceinline__ void ldsm4t(uint32_t& r0, uint32_t& r1, uint32_t& r2,
                                       uint32_t& r3, uint32_t addr) {
    asm volatile("ldmatrix.sync.aligned.m8n8.x4.trans.shared.b16 {%0,%1,%2,%3}, [%4];"
                 : "=r"(r0), "=r"(r1), "=r"(r2), "=r"(r3) : "r"(addr));
}
__device__ __forceinline__ uint32_t packbf2(float a, float b) {
    __nv_bfloat162 h = __floats2bfloat162_rn(a, b);
    return *(uint32_t*)&h;
}

// ---------------- kernels ----------------
__global__ void zero_k() {
    int i = blockIdx.x * blockDim.x + threadIdx.x;
    uint4  zu = make_uint4(0u, 0u, 0u, 0u);
    int4   zi = make_int4(0, 0, 0, 0);
    float4 zf = make_float4(0.f, 0.f, 0.f, 0.f);
    if (i < NNODES * 16 / 4) ((uint4*)g_Cp)[i] = zu;
    if (i < NNODES / 4)      ((int4*)g_outdeg)[i] = zi;
    if (i < NG / 4)          ((int4*)g_cnt)[i] = zi;
    if (i < 128 * IND / 4)   ((float4*)g_part[KBLK])[i] = zf;   // pad partial = 0
}

__global__ void count_k(const int* __restrict__ src, const int* __restrict__ dst,
                        const int* __restrict__ batch) {
    __shared__ int hist[NG];
    int t = threadIdx.x;
    if (t < NG) hist[t] = 0;
    __syncthreads();
    int e = blockIdx.x * blockDim.x + t;
    if (e < NEDGES) {
        int s = src[e];
        int d = dst[e];
        int g = batch[s];
        atomicAdd(&g_Cp[d * 16 + (g >> 2)], 1u << ((g & 3) * 8));
        atomicAdd(&g_outdeg[s], 1);
        atomicAdd(&hist[g], 1);
    }
    __syncthreads();
    if (t < NG && hist[t]) atomicAdd(&g_cnt[t], hist[t]);
}

// Tensor-core pooling GEMM: part[b] = A[128][16nodes...] @ x(nodes)[256]
//   A rows 0-63: dst counts C[g][n];  rows 64-127: outdeg[n] * [batch[n]==g]
__global__ void __launch_bounds__(512, 1) mm_k(const float* __restrict__ x,
                                               const int* __restrict__ batch) {
    __shared__ __align__(16) __nv_bfloat16 Asm[2][128 * 16]; // [m][k], 32B rows
    __shared__ __align__(16) __nv_bfloat16 Bh[2][16 * 256];  // [k][n] swizzled
    __shared__ __align__(16) __nv_bfloat16 Bl[2][16 * 256];

    const uint8_t* C8 = (const uint8_t*)g_Cp;
    int b    = blockIdx.x;
    int n0   = b * NB;
    int tid  = threadIdx.x;
    int lane = tid & 31;
    int warp = tid >> 5;
    int wm   = warp & 7;
    int wn   = warp >> 3;

    int kx = warp;          // x-staging node-in-stage
    int cx = lane;          // 16B block
    int ma = tid & 127;     // A-staging row
    int kh = tid >> 7;      // A-staging k quarter

    float acc[16][4];
#pragma unroll
    for (int i = 0; i < 16; i++)
#pragma unroll
        for (int j = 0; j < 4; j++) acc[i][j] = 0.f;

    const float4* x4 = (const float4*)x;

    int lr   = lane & 7;
    int seg  = lane >> 3;
    int krow = (seg & 1) * 8 + lr;
    int cseg = seg >> 1;
    int krow512 = krow * 512;
    int kmask   = krow & 7;

    float4 pv0, pv1;
    float  pa[4];
    auto prefetch = [&](int s) {
        int nx = n0 + s * 16 + kx;
        if (nx < NNODES) {
            pv0 = x4[(size_t)nx * 64 + cx * 2];
            pv1 = x4[(size_t)nx * 64 + cx * 2 + 1];
        } else {
            pv0 = make_float4(0.f, 0.f, 0.f, 0.f);
            pv1 = pv0;
        }
#pragma unroll
        for (int j = 0; j < 4; j++) {
            int na = n0 + s * 16 + kh * 4 + j;
            float v = 0.f;
            if (na < NNODES) {
                if (ma < NG) {
                    v = (float)C8[na * 64 + ma];
                } else {
                    int g = ma - NG;
                    if (batch[na] == g) v = (float)g_outdeg[na];
                }
            }
            pa[j] = v;
        }
    };
    auto stage = [&](int buf) {
        uint32_t hblk[4], lblk[4];
        float vs[8] = {pv0.x, pv0.y, pv0.z, pv0.w, pv1.x, pv1.y, pv1.z, pv1.w};
        float hs[8], ls[8];
#pragma unroll
        for (int q = 0; q < 8; q++) {
            hs[q] = __bfloat162float(__float2bfloat16_rn(vs[q]));
            ls[q] = vs[q] - hs[q];
        }
#pragma unroll
        for (int q = 0; q < 4; q++) {
            hblk[q] = packbf2(hs[q * 2], hs[q * 2 + 1]);
            lblk[q] = packbf2(ls[q * 2], ls[q * 2 + 1]);
        }
        uint32_t off = (uint32_t)kx * 512 + (uint32_t)((cx ^ (kx & 7)) << 4);
        *(uint4*)((char*)Bh[buf] + off) = *(uint4*)hblk;
        *(uint4*)((char*)Bl[buf] + off) = *(uint4*)lblk;
        uint32_t aw[2];
        aw[0] = packbf2(pa[0], pa[1]);
        aw[1] = packbf2(pa[2], pa[3]);
        *(uint2*)&Asm[buf][ma * 16 + kh * 4] = *(uint2*)aw;
    };

    prefetch(0);
    stage(0);

    for (int s = 0; s < NST; s++) {
        __syncthreads();
        int buf = s & 1;
        if (s + 1 < NST) prefetch(s + 1);

        const uint32_t* A32 = (const uint32_t*)Asm[buf];
        int ai = (wm * 16 + (lane >> 2)) * 8 + (lane & 3);
        uint32_t a0 = A32[ai];
        uint32_t a1 = A32[ai + 64];
        uint32_t a2 = A32[ai + 4];
        uint32_t a3 = A32[ai + 68];

        uint32_t bh_base = smem_u32(Bh[buf]);
        uint32_t bl_base = smem_u32(Bl[buf]);
#pragma unroll
        for (int nb2 = 0; nb2 < 8; nb2++) {
            int nblk = wn * 16 + nb2 * 2 + cseg;
            uint32_t off = (uint32_t)krow512 + (uint32_t)((nblk ^ kmask) << 4);
            uint32_t b0, b1, b2, b3;
            ldsm4t(b0, b1, b2, b3, bh_base + off);
            mma16816(acc[nb2 * 2],     a0, a1, a2, a3, b0, b1);
            mma16816(acc[nb2 * 2 + 1], a0, a1, a2, a3, b2, b3);
            ldsm4t(b0, b1, b2, b3, bl_base + off);
            mma16816(acc[nb2 * 2],     a0, a1, a2, a3, b0, b1);
            mma16816(acc[nb2 * 2 + 1], a0, a1, a2, a3, b2, b3);
        }
        if (s + 1 < NST) stage((s + 1) & 1);
    }

    int r0 = wm * 16 + (lane >> 2);
    int c0 = wn * 128 + (lane & 3) * 2;
#pragma unroll
    for (int nb = 0; nb < 16; nb++) {
        int c = c0 + nb * 8;
        *(float2*)&g_part[b][r0][c]     = make_float2(acc[nb][0], acc[nb][1]);
        *(float2*)&g_part[b][r0 + 8][c] = make_float2(acc[nb][2], acc[nb][3]);
    }
}

// reduce level 1: fold 28 partials per group with full-MLP independent loads
__global__ void reduce1_k() {
    int m   = blockIdx.x;
    int grp = blockIdx.y;
    int f   = threadIdx.x;
    const float* p = &g_part[grp * RSPAN][m][f];
    float v[RSPAN];
#pragma unroll
    for (int q = 0; q < RSPAN; q++) v[q] = p[(size_t)q * 128 * IND];
    float s0 = 0.f, s1 = 0.f, s2 = 0.f, s3 = 0.f;
#pragma unroll
    for (int q = 0; q < RSPAN; q += 4) {
        s0 += v[q]; s1 += v[q + 1]; s2 += v[q + 2]; s3 += v[q + 3];
    }
    g_r1[grp][m][f] = (s0 + s1) + (s2 + s3);
}

// head layer 0: A[r][k] = inv(r) * sum_q g_r1[q][r^64][k]  (folds old reduce2)
__global__ void head0_k(const float* __restrict__ W, const float* __restrict__ bias,
                        float* __restrict__ Pout, float* __restrict__ out) {
    __shared__ float As[16][17];
    __shared__ float Ws[16][17];
    int r0 = blockIdx.y * 16;
    int c0 = blockIdx.x * 16;
    int ty = threadIdx.y, tx = threadIdx.x;
    int r  = r0 + ty;
    int ar = r ^ 64;                 // partial row for this output row
    int g  = r & (NG - 1);
    int cnt = g_cnt[g];
    float inv = cnt > 0 ? 1.0f / (float)cnt : 0.0f;
    float acc = 0.f;
    for (int k0 = 0; k0 < IND; k0 += 16) {
        float a = 0.f;
#pragma unroll
        for (int q = 0; q < RGRP; q++) a += g_r1[q][ar][k0 + tx];
        As[ty][tx] = a * inv;
        Ws[ty][tx] = W[(k0 + ty) * HID + c0 + tx];
        __syncthreads();
#pragma unroll
        for (int kk = 0; kk < 16; kk++) acc += As[ty][kk] * Ws[kk][tx];
        __syncthreads();
    }
    int c = c0 + tx;
    float flag = cnt > 0 ? 1.0f : 0.0f;
    float v = (acc + bias[c]) * flag;
    Pout[r * HID + c] = v;
    int col = ((r < NG) ? 0 : HID) + c;
    out[g * 768 + col] = v;
}

// head layers 1,2
__global__ void head_k(const float* __restrict__ A,
                       const float* __restrict__ W, const float* __restrict__ bias,
                       float* __restrict__ Pout, float* __restrict__ out, int layer) {
    __shared__ float As[16][17];
    __shared__ float Ws[16][17];
    int r0 = blockIdx.y * 16;
    int c0 = blockIdx.x * 16;
    int ty = threadIdx.y, tx = threadIdx.x;
    float acc = 0.f;
    for (int k0 = 0; k0 < HID; k0 += 16) {
        As[ty][tx] = A[(r0 + ty) * HID + k0 + tx];
        Ws[ty][tx] = W[(k0 + ty) * HID + c0 + tx];
        __syncthreads();
#pragma unroll
        for (int kk = 0; kk < 16; kk++) acc += As[ty][kk] * Ws[kk][tx];
        __syncthreads();
    }
    int r = r0 + ty, c = c0 + tx;
    int g = r & (NG - 1);
    float flag = g_cnt[g] > 0 ? 1.0f : 0.0f;
    float v = (acc + bias[c]) * flag;
    if (Pout) Pout[r * HID + c] = v;
    int col = layer * 256 + ((r < NG) ? 0 : HID) + c;
    out[g * 768 + col] = v;
}

// ---------------- launcher ----------------
extern "C" void kernel_launch(void* const* d_in, const int* in_sizes, int n_in,
                              void* d_out, int out_size) {
    const float* x     = (const float*)d_in[0];
    const int*   eidx  = (const int*)d_in[1];
    const int*   batch = (const int*)d_in[2];
    const float* W0 = (const float*)d_in[3];
    const float* b0 = (const float*)d_in[4];
    const float* W1 = (const float*)d_in[5];
    const float* b1 = (const float*)d_in[6];
    const float* W2 = (const float*)d_in[7];
    const float* b2 = (const float*)d_in[8];
    float* out = (float*)d_out;

    const int* src = eidx;
    const int* dst = eidx + NEDGES;

    zero_k<<<(NNODES * 16 / 4 + 255) / 256, 256>>>();
    count_k<<<NEDGES / 256, 256>>>(src, dst, batch);
    mm_k<<<KBLK, 512>>>(x, batch);
    reduce1_k<<<dim3(128, RGRP), IND>>>();

    float *P0, *P1;
    cudaGetSymbolAddress((void**)&P0, g_P);
    P1 = P0 + 128 * HID;

    dim3 hb(16, 16), hg(HID / 16, 128 / 16);
    head0_k<<<hg, hb>>>(W0, b0, P0, out);
    head_k<<<hg, hb>>>(P0, W1, b1, P1, out, 1);
    head_k<<<hg, hb>>>(P1, W2, b2, nullptr, out, 2);
}

// round 9
// speedup vs baseline: 1.0303x; 1.0303x over previous
#include <cuda_runtime.h>
#include <cuda_bf16.h>
#include <cstdint>

#define NNODES 20000
#define NEDGES 640000
#define IND    256
#define HID    128
#define NG     64

#define KBLK   139          // CTAs in split-K
#define KPADB  140          // padded partial count (index 139 zeroed)
#define NB     144          // nodes per CTA
#define NST    9            // stages of 16 nodes
#define RGRP   5            // reduce1 groups
#define RSPAN  28           // partials per reduce1 group (5*28 = 140)

// ---------------- device scratch ----------------
__device__ __align__(16) unsigned g_Cp[NNODES * 16];       // packed u8 counts [node][g], 1.25 MB
__device__ __align__(16) int      g_outdeg[NNODES];
__device__ __align__(16) int      g_cnt[NG];
__device__ __align__(16) float    g_part[KPADB][128][IND]; // split-K partials
__device__ __align__(16) float    g_r1[RGRP][128][IND];    // reduce1 partials
__device__ __align__(16) float    g_P[2][128][HID];        // layer activations

// ---------------- helpers ----------------
__device__ __forceinline__ uint32_t f2tf32(float v) {
    uint32_t t;
    asm("cvt.rna.tf32.f32 %0, %1;" : "=r"(t) : "f"(v));
    return t;
}
__device__ __forceinline__ void mma_tf32(float* d, uint32_t a0, uint32_t a1, uint32_t a2,
                                         uint32_t a3, uint32_t b0, uint32_t b1) {
    asm volatile(
        "mma.sync.aligned.m16n8k8.row.col.f32.tf32.tf32.f32 "
        "{%0,%1,%2,%3},{%4,%5,%6,%7},{%8,%9},{%0,%1,%2,%3};"
        : "+f"(d[0]), "+f"(d[1]), "+f"(d[2]), "+f"(d[3])
        : "r"(a0), "r"(a1), "r"(a2), "r"(a3), "r"(b0), "r"(b1));
}
// B smem layout: element (k, n) of the 16x256 x-tile.
// 16B-block bits XOR-swizzled with (n&7) and (k&3)<<1 -> conflict-free LDS.128/STS.32.
__device__ __forceinline__ uint32_t bofB(int k, int n) {
    int nq  = n & 7;
    int nb  = n >> 3;
    int blk = ((nb >> 2) ^ nq ^ ((k & 3) << 1)) & 7;
    return (uint32_t)(k * 1024 + nq * 128 + blk * 16 + (nb & 3) * 4);
}
// A smem layout (transposed [k][m], 128 m per k-row), swizzled for LDS.32 a-frags.
__device__ __forceinline__ uint32_t bofA(int k, int m) {
    int mb  = m >> 2;
    int blk = (mb & 24) | (((mb & 7) ^ ((k & 3) << 1)) & 7);
    return (uint32_t)(k * 512 + blk * 16 + (m & 3) * 4);
}

// ---------------- kernels ----------------
__global__ void zero_k() {
    int i = blockIdx.x * blockDim.x + threadIdx.x;
    uint4  zu = make_uint4(0u, 0u, 0u, 0u);
    int4   zi = make_int4(0, 0, 0, 0);
    float4 zf = make_float4(0.f, 0.f, 0.f, 0.f);
    if (i < NNODES * 16 / 4) ((uint4*)g_Cp)[i] = zu;
    if (i < NNODES / 4)      ((int4*)g_outdeg)[i] = zi;
    if (i < NG / 4)          ((int4*)g_cnt)[i] = zi;
    if (i < 128 * IND / 4)   ((float4*)g_part[KBLK])[i] = zf;   // pad partial = 0
}

__global__ void count_k(const int* __restrict__ src, const int* __restrict__ dst,
                        const int* __restrict__ batch) {
    __shared__ int hist[NG];
    int t = threadIdx.x;
    if (t < NG) hist[t] = 0;
    __syncthreads();
    int e4 = blockIdx.x * blockDim.x + t;          // NEDGES/4 threads total
    int4 s4 = ((const int4*)src)[e4];
    int4 d4 = ((const int4*)dst)[e4];
    int ss[4] = {s4.x, s4.y, s4.z, s4.w};
    int dd[4] = {d4.x, d4.y, d4.z, d4.w};
#pragma unroll
    for (int u = 0; u < 4; u++) {
        int g = batch[ss[u]];
        atomicAdd(&g_Cp[dd[u] * 16 + (g >> 2)], 1u << ((g & 3) * 8));
        atomicAdd(&g_outdeg[ss[u]], 1);
        atomicAdd(&hist[g], 1);
    }
    __syncthreads();
    if (t < NG && hist[t]) atomicAdd(&g_cnt[t], hist[t]);
}

// TF32 tensor-core pooling GEMM: part[b] = A[128][16nodes...] @ x(nodes)[256]
//   A rows 0-63: dst counts; rows 64-127: outdeg * [batch==g]. Single pass (no hi/lo).
__global__ void __launch_bounds__(512, 1) mm_k(const float* __restrict__ x,
                                               const int* __restrict__ batch) {
    __shared__ __align__(16) float Bsm[2][16 * 256];   // 32 KB (tf32 bits)
    __shared__ __align__(16) float Atr[2][16 * 128];   // 16 KB (tf32 bits, [k][m])

    const uint8_t* C8 = (const uint8_t*)g_Cp;
    int b    = blockIdx.x;
    int n0   = b * NB;
    int tid  = threadIdx.x;
    int lane = tid & 31;
    int warp = tid >> 5;
    int wm   = warp & 7;      // m-tile: rows wm*16..+15
    int wn   = warp >> 3;     // n-half: cols wn*128..+127
    int kq   = lane & 3;
    int r8   = lane >> 2;

    int kx = warp;            // x-staging node-in-stage
    int cx = lane;            // 8 features n = cx*8..+7
    int ma = tid & 127;       // A-staging row
    int kh = tid >> 7;        // A-staging k quarter

    float acc[16][4];
#pragma unroll
    for (int i = 0; i < 16; i++)
#pragma unroll
        for (int j = 0; j < 4; j++) acc[i][j] = 0.f;

    const float4* x4 = (const float4*)x;

    float4 pv0, pv1;
    float  pa[4];
    auto prefetch = [&](int s) {
        int nx = n0 + s * 16 + kx;
        if (nx < NNODES) {
            pv0 = x4[(size_t)nx * 64 + cx * 2];
            pv1 = x4[(size_t)nx * 64 + cx * 2 + 1];
        } else {
            pv0 = make_float4(0.f, 0.f, 0.f, 0.f);
            pv1 = pv0;
        }
#pragma unroll
        for (int j = 0; j < 4; j++) {
            int na = n0 + s * 16 + kh * 4 + j;
            float v = 0.f;
            if (na < NNODES) {
                if (ma < NG) {
                    v = (float)C8[na * 64 + ma];
                } else {
                    int g = ma - NG;
                    if (batch[na] == g) v = (float)g_outdeg[na];
                }
            }
            pa[j] = v;
        }
    };
    auto stage = [&](int buf) {
        float vs[8] = {pv0.x, pv0.y, pv0.z, pv0.w, pv1.x, pv1.y, pv1.z, pv1.w};
        char* Bb = (char*)Bsm[buf];
        char* Ab = (char*)Atr[buf];
#pragma unroll
        for (int j = 0; j < 8; j++)
            *(uint32_t*)(Bb + bofB(kx, cx * 8 + j)) = f2tf32(vs[j]);
#pragma unroll
        for (int j = 0; j < 4; j++)
            *(uint32_t*)(Ab + bofA(kh * 4 + j, ma)) = f2tf32(pa[j]);
    };

    prefetch(0);
    stage(0);

    for (int s = 0; s < NST; s++) {
        __syncthreads();
        int buf = s & 1;
        if (s + 1 < NST) prefetch(s + 1);

        const char* Ab = (const char*)Atr[buf];
        const char* Bb = (const char*)Bsm[buf];
#pragma unroll
        for (int ko = 0; ko < 16; ko += 8) {
            uint32_t a0 = *(const uint32_t*)(Ab + bofA(ko + kq,     wm * 16 + r8));
            uint32_t a1 = *(const uint32_t*)(Ab + bofA(ko + kq,     wm * 16 + r8 + 8));
            uint32_t a2 = *(const uint32_t*)(Ab + bofA(ko + 4 + kq, wm * 16 + r8));
            uint32_t a3 = *(const uint32_t*)(Ab + bofA(ko + 4 + kq, wm * 16 + r8 + 8));
#pragma unroll
            for (int g0 = 0; g0 < 4; g0++) {
                int nbase = (wn * 16 + g0 * 4) * 8 + r8;
                float4 f0 = *(const float4*)(Bb + bofB(ko + kq,     nbase));
                float4 f1 = *(const float4*)(Bb + bofB(ko + 4 + kq, nbase));
                const float b0v[4] = {f0.x, f0.y, f0.z, f0.w};
                const float b1v[4] = {f1.x, f1.y, f1.z, f1.w};
#pragma unroll
                for (int t = 0; t < 4; t++) {
                    mma_tf32(acc[g0 * 4 + t], a0, a1, a2, a3,
                             __float_as_uint(b0v[t]), __float_as_uint(b1v[t]));
                }
            }
        }
        if (s + 1 < NST) stage((s + 1) & 1);
    }

    // epilogue: c-frag mapping (row = wm*16 + lane/4, col = wn*128 + nb*8 + (lane%4)*2)
    int r0 = wm * 16 + r8;
    int c0 = wn * 128 + kq * 2;
#pragma unroll
    for (int nb = 0; nb < 16; nb++) {
        int c = c0 + nb * 8;
        *(float2*)&g_part[b][r0][c]     = make_float2(acc[nb][0], acc[nb][1]);
        *(float2*)&g_part[b][r0 + 8][c] = make_float2(acc[nb][2], acc[nb][3]);
    }
}

// reduce level 1: fold 28 partials per group with full-MLP independent loads
__global__ void reduce1_k() {
    int m   = blockIdx.x;
    int grp = blockIdx.y;
    int f   = threadIdx.x;
    const float* p = &g_part[grp * RSPAN][m][f];
    float v[RSPAN];
#pragma unroll
    for (int q = 0; q < RSPAN; q++) v[q] = p[(size_t)q * 128 * IND];
    float s0 = 0.f, s1 = 0.f, s2 = 0.f, s3 = 0.f;
#pragma unroll
    for (int q = 0; q < RSPAN; q += 4) {
        s0 += v[q]; s1 += v[q + 1]; s2 += v[q + 2]; s3 += v[q + 3];
    }
    g_r1[grp][m][f] = (s0 + s1) + (s2 + s3);
}

// head layer 0: A[r][k] = inv(r) * sum_q g_r1[q][r^64][k]  (folds final reduce)
__global__ void head0_k(const float* __restrict__ W, const float* __restrict__ bias,
                        float* __restrict__ Pout, float* __restrict__ out) {
    __shared__ float As[16][17];
    __shared__ float Ws[16][17];
    int r0 = blockIdx.y * 16;
    int c0 = blockIdx.x * 16;
    int ty = threadIdx.y, tx = threadIdx.x;
    int r  = r0 + ty;
    int ar = r ^ 64;
    int g  = r & (NG - 1);
    int cnt = g_cnt[g];
    float inv = cnt > 0 ? 1.0f / (float)cnt : 0.0f;
    float acc = 0.f;
    for (int k0 = 0; k0 < IND; k0 += 16) {
        float a = 0.f;
#pragma unroll
        for (int q = 0; q < RGRP; q++) a += g_r1[q][ar][k0 + tx];
        As[ty][tx] = a * inv;
        Ws[ty][tx] = W[(k0 + ty) * HID + c0 + tx];
        __syncthreads();
#pragma unroll
        for (int kk = 0; kk < 16; kk++) acc += As[ty][kk] * Ws[kk][tx];
        __syncthreads();
    }
    int c = c0 + tx;
    float flag = cnt > 0 ? 1.0f : 0.0f;
    float v = (acc + bias[c]) * flag;
    Pout[r * HID + c] = v;
    int col = ((r < NG) ? 0 : HID) + c;
    out[g * 768 + col] = v;
}

// head layers 1,2
__global__ void head_k(const float* __restrict__ A,
                       const float* __restrict__ W, const float* __restrict__ bias,
                       float* __restrict__ Pout, float* __restrict__ out, int layer) {
    __shared__ float As[16][17];
    __shared__ float Ws[16][17];
    int r0 = blockIdx.y * 16;
    int c0 = blockIdx.x * 16;
    int ty = threadIdx.y, tx = threadIdx.x;
    float acc = 0.f;
    for (int k0 = 0; k0 < HID; k0 += 16) {
        As[ty][tx] = A[(r0 + ty) * HID + k0 + tx];
        Ws[ty][tx] = W[(k0 + ty) * HID + c0 + tx];
        __syncthreads();
#pragma unroll
        for (int kk = 0; kk < 16; kk++) acc += As[ty][kk] * Ws[kk][tx];
        __syncthreads();
    }
    int r = r0 + ty, c = c0 + tx;
    int g = r & (NG - 1);
    float flag = g_cnt[g] > 0 ? 1.0f : 0.0f;
    float v = (acc + bias[c]) * flag;
    if (Pout) Pout[r * HID + c] = v;
    int col = layer * 256 + ((r < NG) ? 0 : HID) + c;
    out[g * 768 + col] = v;
}

// ---------------- launcher ----------------
extern "C" void kernel_launch(void* const* d_in, const int* in_sizes, int n_in,
                              void* d_out, int out_size) {
    const float* x     = (const float*)d_in[0];
    const int*   eidx  = (const int*)d_in[1];
    const int*   batch = (const int*)d_in[2];
    const float* W0 = (const float*)d_in[3];
    const float* b0 = (const float*)d_in[4];
    const float* W1 = (const float*)d_in[5];
    const float* b1 = (const float*)d_in[6];
    const float* W2 = (const float*)d_in[7];
    const float* b2 = (const float*)d_in[8];
    float* out = (float*)d_out;

    const int* src = eidx;
    const int* dst = eidx + NEDGES;

    zero_k<<<(NNODES * 16 / 4 + 255) / 256, 256>>>();
    count_k<<<NEDGES / 4 / 256, 256>>>(src, dst, batch);
    mm_k<<<KBLK, 512>>>(x, batch);
    reduce1_k<<<dim3(128, RGRP), IND>>>();

    float *P0, *P1;
    cudaGetSymbolAddress((void**)&P0, g_P);
    P1 = P0 + 128 * HID;

    dim3 hb(16, 16), hg(HID / 16, 128 / 16);
    head0_k<<<hg, hb>>>(W0, b0, P0, out);
    head_k<<<hg, hb>>>(P0, W1, b1, P1, out, 1);
    head_k<<<hg, hb>>>(P1, W2, b2, nullptr, out, 2);
}